// round 15
// baseline (speedup 1.0000x reference)
#include <cuda_runtime.h>
#include <cuda_fp16.h>
#include <cstdint>

// ---------------- problem constants ----------------
#define HD    256
#define BSZ   256
#define MAXN  128
#define MAXE  256
#define MAXC  64
#define NLAY  4
#define OUTD  10
#define PN    131072
#define PE    98304
#define QE    131072
#define QC    65536

#define NN (BSZ*MAXN)
#define NE (BSZ*MAXE)
#define NC (BSZ*MAXC)

#define WTF ((size_t)38*65536 + (size_t)3*512*256)

// ---------------- device scratch ----------------
__device__ float g_SN[2][(size_t)NN*HD];
__device__ float g_SE[2][(size_t)NE*HD];
__device__ float g_SC[2][(size_t)NC*HD];
__device__ float g_BDC[2][(size_t)NC*HD];
__device__ float g_VCb[2][(size_t)NC*HD];
__device__ float g_UN[(size_t)NN*HD];
__device__ float g_VN[(size_t)NE*HD];
__device__ float g_UE[(size_t)NE*HD];
__device__ float g_BDNE[(size_t)NN*HD];
__device__ float g_BDFC[(size_t)NC*HD];
__device__ float g_GPN[(size_t)NN*HD];
__device__ float g_GPE[(size_t)NE*HD];
__device__ float g_GPC[(size_t)NC*HD];
__device__ unsigned g_maske[(size_t)BSZ*MAXE*MAXN/32];
__device__ unsigned g_maskc[(size_t)BSZ*MAXC*MAXE/32];
__device__ unsigned char g_flage[QE];
__device__ unsigned char g_flagc[QC];
__device__ float g_pooled[3][(size_t)BSZ*HD];
__device__ float g_hs[6][(size_t)BSZ*256];
__device__ __align__(16) __half g_WTH[2*WTF];

// ---------------- PTX helpers (base ISA only) ----------------
__device__ __forceinline__ uint32_t s2u(const void* p) {
    uint32_t a;
    asm("{ .reg .u64 t; cvta.to.shared.u64 t, %1; cvt.u32.u64 %0, t; }"
        : "=r"(a) : "l"(p));
    return a;
}

__device__ __forceinline__ void cp16(uint32_t sa, const void* g) {
    asm volatile("cp.async.cg.shared.global [%0], [%1], 16;" :: "r"(sa), "l"(g));
}
#define CP_COMMIT() asm volatile("cp.async.commit_group;" ::: "memory")
#define CP_WAIT(n)  asm volatile("cp.async.wait_group %0;" :: "n"(n) : "memory")

__device__ __forceinline__ void mma16(float* d, const uint32_t* a, const uint32_t* b) {
    asm volatile(
        "mma.sync.aligned.m16n8k16.row.col.f32.f16.f16.f32 "
        "{%0,%1,%2,%3}, {%4,%5,%6,%7}, {%8,%9}, {%0,%1,%2,%3};"
        : "+f"(d[0]), "+f"(d[1]), "+f"(d[2]), "+f"(d[3])
        : "r"(a[0]), "r"(a[1]), "r"(a[2]), "r"(a[3]), "r"(b[0]), "r"(b[1]));
}

__device__ __forceinline__ void ldm_x4(uint32_t* r, uint32_t sa) {
    asm volatile("ldmatrix.sync.aligned.m8n8.x4.shared.b16 {%0,%1,%2,%3}, [%4];"
                 : "=r"(r[0]), "=r"(r[1]), "=r"(r[2]), "=r"(r[3]) : "r"(sa));
}

__device__ __forceinline__ void red4(float* p, float4 v) {
    asm volatile("red.global.add.v4.f32 [%0], {%1, %2, %3, %4};"
                 :: "l"(p), "f"(v.x), "f"(v.y), "f"(v.z), "f"(v.w) : "memory");
}

__device__ __forceinline__ uint32_t h2u(__half2 h) {
    return *reinterpret_cast<uint32_t*>(&h);
}

// ---------------- job table ----------------
#define MAXJ 12
struct JobPack {
    const float*  A[MAXJ];
    const float*  A2[MAXJ];
    const __half* B[MAXJ];
    float*        C[MAXJ];
    const float*  bias[MAXJ];
    int cum[MAXJ + 1];
    int flags[MAXJ];            // 1 reluA, 2 reluE, 4 accC
};

// ---------------- fp16x3 job-table tensor-core GEMM ----------------
#define PITCH 112
#define A_PLANE (128*PITCH)
#define B_PLANE (256*PITCH)
#define STAGE_B (2*A_PLANE + 2*B_PLANE)
#define MMAG_SMEM (2*STAGE_B)

__global__ __launch_bounds__(256, 1) void mma_jobs(JobPack P)
{
    extern __shared__ __align__(16) char smem[];
    const int tid = threadIdx.x;
    const int wid = tid >> 5, lane = tid & 31;
    const int wm = wid & 1;
    const int wn = wid >> 1;
    const int g = lane >> 2, t = lane & 3;
    const uint32_t sb = s2u(smem);

    int ji = 0;
    #pragma unroll
    for (int i = 1; i < MAXJ; i++)
        if ((int)blockIdx.x >= P.cum[i]) ji++;
    const int m0 = (blockIdx.x - P.cum[ji]) * 128;

    const float*  A    = P.A[ji];
    const float*  A2   = P.A2[ji];
    const __half* B0   = P.B[ji];
    const __half* B1   = B0 + WTF;
    float*        C    = P.C[ji];
    const float*  bias = P.bias[ji];
    const int     fl   = P.flags[ji];
    const int reluA = fl & 1, reluE = fl & 2, accC = fl & 4;

    const float* Ag  = A + (size_t)m0 * 256;
    const float* A2g = A2 ? A2 + (size_t)m0 * 256 : nullptr;

    float acc4[4][8][4];
    #pragma unroll
    for (int i = 0; i < 4; i++)
        #pragma unroll
        for (int j = 0; j < 8; j++)
            #pragma unroll
            for (int k = 0; k < 4; k++) acc4[i][j][k] = 0.f;

    float4 ra[4];

    auto ldgA = [&](int c) {
        #pragma unroll
        for (int i = 0; i < 4; i++) {
            int idx = i * 256 + tid;
            int row = idx >> 3, q = idx & 7;
            ra[i] = *reinterpret_cast<const float4*>(
                Ag + (size_t)row * 256 + c * 32 + q * 4);
        }
        if (A2g) {
            #pragma unroll
            for (int i = 0; i < 4; i++) {
                int idx = i * 256 + tid;
                int row = idx >> 3, q = idx & 7;
                float4 u = *reinterpret_cast<const float4*>(
                    A2g + (size_t)row * 256 + c * 32 + q * 4);
                ra[i].x += u.x; ra[i].y += u.y; ra[i].z += u.z; ra[i].w += u.w;
            }
        }
    };
    auto cvtstsA = [&](int stage) {
        #pragma unroll
        for (int i = 0; i < 4; i++) {
            int idx = i * 256 + tid;
            int row = idx >> 3, q = idx & 7;
            float4 x = ra[i];
            if (reluA) {
                x.x = fmaxf(x.x, 0.f); x.y = fmaxf(x.y, 0.f);
                x.z = fmaxf(x.z, 0.f); x.w = fmaxf(x.w, 0.f);
            }
            __half2 h0a = __floats2half2_rn(x.x, x.y);
            __half2 h0b = __floats2half2_rn(x.z, x.w);
            float2 f0a = __half22float2(h0a);
            float2 f0b = __half22float2(h0b);
            __half2 h1a = __floats2half2_rn(x.x - f0a.x, x.y - f0a.y);
            __half2 h1b = __floats2half2_rn(x.z - f0b.x, x.w - f0b.y);
            uint32_t off = (uint32_t)(row * PITCH + q * 8);
            *reinterpret_cast<uint2*>(smem + stage * STAGE_B + off) =
                make_uint2(h2u(h0a), h2u(h0b));
            *reinterpret_cast<uint2*>(smem + stage * STAGE_B + A_PLANE + off) =
                make_uint2(h2u(h1a), h2u(h1b));
        }
    };
    auto cpB = [&](int c, int stage) {
        uint32_t b0 = sb + (uint32_t)(stage * STAGE_B + 2 * A_PLANE);
        uint32_t b1 = b0 + B_PLANE;
        #pragma unroll
        for (int i = 0; i < 8; i++) {
            int idx = i * 256 + tid;
            int row = idx >> 3;
            int s = idx & 7;
            int plane = s >> 2, seg = s & 3;
            uint32_t dst = (plane ? b1 : b0) + (uint32_t)(row * PITCH + seg * 16);
            const __half* src = (plane ? B1 : B0) + (size_t)row * 256 + c * 32 + seg * 8;
            cp16(dst, src);
        }
        CP_COMMIT();
    };

    const int ar0 = wm * 64;
    const int bc0 = wn * 64;
    const uint32_t aoff = (uint32_t)((ar0 + (lane & 15)) * PITCH + (lane >> 4) * 16);
    const int grp = lane >> 3;
    const uint32_t boff = (uint32_t)((bc0 + ((grp >> 1) << 3) + (lane & 7)) * PITCH
                                     + (grp & 1) * 16);

    ldgA(0); cvtstsA(0); cpB(0, 0);
    ldgA(1);

    #pragma unroll
    for (int c = 0; c < 8; c++) {
        CP_WAIT(0);
        __syncthreads();
        if (c < 7) cpB(c + 1, (c + 1) & 1);

        const uint32_t st = sb + (uint32_t)(c & 1) * STAGE_B;

        #pragma unroll
        for (int ks = 0; ks < 2; ks++) {
            const uint32_t ko = ks * 32;
            uint32_t a0[4][4], a1[4][4];
            #pragma unroll
            for (int mt = 0; mt < 4; mt++) {
                uint32_t ad = st + aoff + (uint32_t)(mt * 16 * PITCH) + ko;
                ldm_x4(a0[mt], ad);
                ldm_x4(a1[mt], ad + A_PLANE);
            }
            uint32_t b0r[8][2], b1r[8][2];
            #pragma unroll
            for (int q = 0; q < 4; q++) {
                uint32_t bd = st + 2 * A_PLANE + boff + (uint32_t)(q * 16 * PITCH) + ko;
                uint32_t r[4];
                ldm_x4(r, bd);
                b0r[2*q][0] = r[0]; b0r[2*q][1] = r[1];
                b0r[2*q+1][0] = r[2]; b0r[2*q+1][1] = r[3];
                ldm_x4(r, bd + B_PLANE);
                b1r[2*q][0] = r[0]; b1r[2*q][1] = r[1];
                b1r[2*q+1][0] = r[2]; b1r[2*q+1][1] = r[3];
            }
            #pragma unroll
            for (int mt = 0; mt < 4; mt++)
                #pragma unroll
                for (int nt = 0; nt < 8; nt++)
                    mma16(acc4[mt][nt], a0[mt], b0r[nt]);
            #pragma unroll
            for (int mt = 0; mt < 4; mt++)
                #pragma unroll
                for (int nt = 0; nt < 8; nt++)
                    mma16(acc4[mt][nt], a0[mt], b1r[nt]);
            #pragma unroll
            for (int mt = 0; mt < 4; mt++)
                #pragma unroll
                for (int nt = 0; nt < 8; nt++)
                    mma16(acc4[mt][nt], a1[mt], b0r[nt]);
        }

        if (c < 7) cvtstsA((c + 1) & 1);
        if (c < 6) ldgA(c + 2);
    }

    #pragma unroll
    for (int mt = 0; mt < 4; mt++) {
        #pragma unroll
        for (int nt = 0; nt < 8; nt++) {
            const int col = wn * 64 + nt * 8 + 2 * t;
            #pragma unroll
            for (int h = 0; h < 2; h++) {
                const int row = m0 + wm * 64 + mt * 16 + g + h * 8;
                const size_t off = (size_t)row * 256 + col;
                float v0 = acc4[mt][nt][2 * h];
                float v1 = acc4[mt][nt][2 * h + 1];
                if (bias)  { v0 += bias[col]; v1 += bias[col + 1]; }
                if (reluE) { v0 = fmaxf(v0, 0.f); v1 = fmaxf(v1, 0.f); }
                if (accC)  { float2 a = *reinterpret_cast<const float2*>(C + off);
                             v0 += a.x; v1 += a.y; }
                *reinterpret_cast<float2*>(C + off) = make_float2(v0, v1);
            }
        }
    }
}

// ---------------- weight transpose + fp16 h0/h1 split ----------------
__global__ void transpose_all(
    const float* __restrict__ Wself, const float* __restrict__ Wupx,
    const float* __restrict__ Wupa,  const float* __restrict__ Wb,
    const float* __restrict__ Wp,    const float* __restrict__ Wp_r,
    const float* __restrict__ W1,    __half* __restrict__ out)
{
    int z = blockIdx.z;
    const float* I;
    __half* O;
    int N;
    if (z < 12)      { I = Wself + (size_t)z * 65536;        O = out + (size_t)z * 65536;  N = 256; }
    else if (z < 20) { I = Wupx + (size_t)(z - 12) * 65536;  O = out + (size_t)z * 65536;  N = 256; }
    else if (z < 28) { I = Wupa + (size_t)(z - 20) * 65536;  O = out + (size_t)z * 65536;  N = 256; }
    else if (z < 36) { I = Wb + (size_t)(z - 28) * 65536;    O = out + (size_t)z * 65536;  N = 256; }
    else if (z == 36){ I = Wp;                               O = out + (size_t)36 * 65536; N = 256; }
    else if (z == 37){ I = Wp_r;                             O = out + (size_t)37 * 65536; N = 256; }
    else             { I = W1 + (size_t)(z - 38) * 512 * 256;
                       O = out + (size_t)38 * 65536 + (size_t)(z - 38) * 512 * 256; N = 512; }
    const int K = 256;
    int n0 = blockIdx.x * 32, k0 = blockIdx.y * 32;
    if (n0 >= N) return;
    __shared__ float tbuf[32][33];
    int x = threadIdx.x, y = threadIdx.y;
    #pragma unroll
    for (int dy = 0; dy < 32; dy += 8)
        tbuf[y + dy][x] = I[(size_t)(k0 + y + dy) * N + n0 + x];
    __syncthreads();
    #pragma unroll
    for (int dy = 0; dy < 32; dy += 8) {
        float w = tbuf[x][y + dy];
        __half h0 = __float2half_rn(w);
        __half h1 = __float2half_rn(w - __half2float(h0));
        size_t o = (size_t)(n0 + y + dy) * K + k0 + x;
        O[o] = h0;
        O[o + WTF] = h1;
    }
}

// ---------------- merged dedup ----------------
__global__ void dedup2_kernel(
    const int* __restrict__ eb_b, const int* __restrict__ eb_i,
    const int* __restrict__ eb_j,
    const int* __restrict__ cb_b, const int* __restrict__ cb_i,
    const int* __restrict__ cb_j,
    unsigned* __restrict__ maske, unsigned* __restrict__ maskc,
    unsigned char* __restrict__ flage, unsigned char* __restrict__ flagc)
{
    int q = blockIdx.x * blockDim.x + threadIdx.x;
    if (q < QE) {
        unsigned flat = ((unsigned)eb_b[q] * MAXE + eb_i[q]) * MAXN + eb_j[q];
        unsigned bit = 1u << (flat & 31u);
        unsigned old = atomicOr(&maske[flat >> 5], bit);
        flage[q] = (old & bit) ? 0 : 1;
    } else {
        int r = q - QE;
        if (r < QC) {
            unsigned flat = ((unsigned)cb_b[r] * MAXC + cb_i[r]) * MAXE + cb_j[r];
            unsigned bit = 1u << (flat & 31u);
            unsigned old = atomicOr(&maskc[flat >> 5], bit);
            flagc[r] = (old & bit) ? 0 : 1;
        }
    }
}

// ---------------- cell-boundary scatter ----------------
__global__ void bd_scatter_kernel(
    const float* __restrict__ X, float* __restrict__ out,
    const unsigned char* __restrict__ flag,
    const int* __restrict__ qb, const int* __restrict__ qi, const int* __restrict__ qj,
    int Q, int mult_i, int mult_j, int reluX)
{
    int w = (blockIdx.x * blockDim.x + threadIdx.x) >> 5;
    int lane = threadIdx.x & 31;
    if (w >= Q) return;
    if (!flag[w]) return;
    int b = qb[w];
    size_t dst = ((size_t)b * mult_i + qi[w]) * HD;
    size_t src = ((size_t)b * mult_j + qj[w]) * HD;
    #pragma unroll
    for (int t = 0; t < 2; t++) {
        int c = (lane << 2) + (t << 7);
        float4 v = *reinterpret_cast<const float4*>(X + src + c);
        if (reluX) {
            v.x = fmaxf(v.x, 0.f); v.y = fmaxf(v.y, 0.f);
            v.z = fmaxf(v.z, 0.f); v.w = fmaxf(v.w, 0.f);
        }
        red4(out + dst + c, v);
    }
}

// ---------------- fused per-layer scatter: 3 segments ----------------
#define FS_SEG0 (PN/8)
#define FS_SEG1 (FS_SEG0 + PE/8)
#define FS_GRID (FS_SEG1 + QE/8)

__global__ void fused_scatter(
    const float* __restrict__ UN, const float* __restrict__ VN,
    float* __restrict__ SN_,
    const float* __restrict__ UE, const float* __restrict__ VC,
    float* __restrict__ SE_,
    const float* __restrict__ BDNE, const unsigned char* __restrict__ flage,
    const int* __restrict__ nb, const int* __restrict__ ni,
    const int* __restrict__ nj, const int* __restrict__ na,
    const int* __restrict__ pb, const int* __restrict__ pi,
    const int* __restrict__ pj, const int* __restrict__ pa,
    const int* __restrict__ qb, const int* __restrict__ qi,
    const int* __restrict__ qj)
{
    const int blk = blockIdx.x;
    const int lane = threadIdx.x & 31;

    if (blk < FS_SEG0) {
        int w = blk * 8 + (threadIdx.x >> 5);
        int b = nb[w];
        size_t dst = ((size_t)b * MAXN + ni[w]) * HD;
        size_t src = ((size_t)b * MAXN + nj[w]) * HD;
        size_t att = ((size_t)b * MAXE + na[w]) * HD;
        #pragma unroll
        for (int t = 0; t < 2; t++) {
            int c = (lane << 2) + (t << 7);
            float4 u = *reinterpret_cast<const float4*>(UN + src + c);
            float4 v = *reinterpret_cast<const float4*>(VN + att + c);
            float4 r;
            r.x = fmaxf(u.x + v.x, 0.f);
            r.y = fmaxf(u.y + v.y, 0.f);
            r.z = fmaxf(u.z + v.z, 0.f);
            r.w = fmaxf(u.w + v.w, 0.f);
            red4(SN_ + dst + c, r);
        }
    } else if (blk < FS_SEG1) {
        int w = (blk - FS_SEG0) * 8 + (threadIdx.x >> 5);
        int b = pb[w];
        size_t dst = ((size_t)b * MAXE + pi[w]) * HD;
        size_t src = ((size_t)b * MAXE + pj[w]) * HD;
        size_t att = ((size_t)b * MAXC + pa[w]) * HD;
        #pragma unroll
        for (int t = 0; t < 2; t++) {
            int c = (lane << 2) + (t << 7);
            float4 u = *reinterpret_cast<const float4*>(UE + src + c);
            float4 v = *reinterpret_cast<const float4*>(VC + att + c);
            float4 r;
            r.x = fmaxf(u.x + v.x, 0.f);
            r.y = fmaxf(u.y + v.y, 0.f);
            r.z = fmaxf(u.z + v.z, 0.f);
            r.w = fmaxf(u.w + v.w, 0.f);
            red4(SE_ + dst + c, r);
        }
    } else {
        int w = (blk - FS_SEG1) * 8 + (threadIdx.x >> 5);
        if (!flage[w]) return;
        int b = qb[w];
        size_t dst = ((size_t)b * MAXE + qi[w]) * HD;
        size_t src = ((size_t)b * MAXN + qj[w]) * HD;
        #pragma unroll
        for (int t = 0; t < 2; t++) {
            int c = (lane << 2) + (t << 7);
            float4 v = *reinterpret_cast<const float4*>(BDNE + src + c);
            red4(SE_ + dst + c, v);
        }
    }
}

// ---------------- merged gated pooling ----------------
__global__ void pool3_kernel(
    const float* __restrict__ Xn, const float* __restrict__ Xe,
    const float* __restrict__ Xc, const float* __restrict__ Xc2,
    const float* __restrict__ Gn1, const float* __restrict__ Ge1,
    const float* __restrict__ Gc1,
    const float* __restrict__ Gn2, const float* __restrict__ Ge2,
    const float* __restrict__ Gc2,
    const float* __restrict__ bp, float* __restrict__ out)
{
    const int seg = blockIdx.x >> 8;
    const int b = blockIdx.x & 255;
    const int h = threadIdx.x;
    const float* X  = (seg == 0) ? Xn  : ((seg == 1) ? Xe  : Xc);
    const float* X2 = (seg == 2) ? Xc2 : nullptr;
    const float* G1 = (seg == 0) ? Gn1 : ((seg == 1) ? Ge1 : Gc1);
    const float* G2 = (seg == 0) ? Gn2 : ((seg == 1) ? Ge2 : Gc2);
    const int per = (seg == 0) ? MAXN : ((seg == 1) ? MAXE : MAXC);
    float bias = bp[h];
    float acc = 0.f;
    size_t base = (size_t)b * per * HD + h;
    for (int n = 0; n < per; n++) {
        size_t idx = base + (size_t)n * HD;
        float gg = G1[idx] + G2[idx] + bias;
        float w = 1.f / (1.f + expf(-gg));
        float x = X[idx];
        if (X2) x += X2[idx];
        x = fmaxf(x, 0.f);
        acc = fmaf(w, x, acc);
    }
    out[(size_t)seg * BSZ * HD + (size_t)b * HD + h] = acc;
}

// ---------------- final projection ----------------
__global__ void final_out_kernel(
    const float* __restrict__ hs, const float* __restrict__ W2,
    const float* __restrict__ b2, float* __restrict__ out)
{
    int b = blockIdx.x;
    int o = threadIdx.x;
    if (o >= OUTD) return;
    const size_t S = (size_t)BSZ * 256;
    float acc = b2[o];
    for (int k = 0; k < 256; k++) {
        size_t bk = (size_t)b * 256 + k;
        float a = hs[0 * S + bk] + hs[2 * S + bk] + hs[4 * S + bk];
        float c = hs[1 * S + bk] + hs[3 * S + bk] + hs[5 * S + bk];
        acc = fmaf(a, W2[k * OUTD + o], acc);
        acc = fmaf(c, W2[(256 + k) * OUTD + o], acc);
    }
    out[b * OUTD + o] = acc;
}

// ---------------- host side ----------------
static void* vsym(const void* symbol) {
    void* p = nullptr;
    cudaGetSymbolAddress(&p, symbol);
    return p;
}
static float* fsym(const void* s) { return (float*)vsym(s); }

extern "C" void kernel_launch(void* const* d_in, const int* in_sizes, int n_in,
                              void* d_out, int out_size)
{
    (void)in_sizes; (void)n_in; (void)out_size;

    // persistent side stream + events (created on first call, before capture)
    static cudaStream_t s2 = nullptr;
    static cudaEvent_t evS = nullptr, evM0 = nullptr;
    static cudaEvent_t evFS[3] = {};
    static cudaEvent_t evC[5] = {};        // evC[1..4]
    if (!s2) {
        cudaStreamCreateWithFlags(&s2, cudaStreamNonBlocking);
        cudaEventCreateWithFlags(&evS,  cudaEventDisableTiming);
        cudaEventCreateWithFlags(&evM0, cudaEventDisableTiming);
        for (int i = 0; i < 3; i++) cudaEventCreateWithFlags(&evFS[i], cudaEventDisableTiming);
        for (int i = 1; i < 5; i++) cudaEventCreateWithFlags(&evC[i], cudaEventDisableTiming);
    }

    cudaFuncSetAttribute(mma_jobs, cudaFuncAttributeMaxDynamicSharedMemorySize, MMAG_SMEM);

    const float* x_n   = (const float*)d_in[0];
    const float* x_e   = (const float*)d_in[1];
    const float* x_c   = (const float*)d_in[2];
    const int* n_up_b  = (const int*)d_in[3];
    const int* n_up_i  = (const int*)d_in[4];
    const int* n_up_j  = (const int*)d_in[5];
    const int* n_up_e  = (const int*)d_in[6];
    const int* e_up_b  = (const int*)d_in[7];
    const int* e_up_i  = (const int*)d_in[8];
    const int* e_up_j  = (const int*)d_in[9];
    const int* e_up_c  = (const int*)d_in[10];
    const int* eb_b    = (const int*)d_in[11];
    const int* eb_i    = (const int*)d_in[12];
    const int* eb_j    = (const int*)d_in[13];
    const int* cb_b    = (const int*)d_in[14];
    const int* cb_i    = (const int*)d_in[15];
    const int* cb_j    = (const int*)d_in[16];
    const float* Wself = (const float*)d_in[17];
    const float* bself = (const float*)d_in[18];
    const float* Wupx  = (const float*)d_in[19];
    const float* Wupa  = (const float*)d_in[20];
    const float* Wb    = (const float*)d_in[21];
    const float* Wp    = (const float*)d_in[22];
    const float* Wp_r  = (const float*)d_in[23];
    const float* bp    = (const float*)d_in[24];
    const float* W1    = (const float*)d_in[25];
    const float* b1    = (const float*)d_in[26];
    const float* W2    = (const float*)d_in[27];
    const float* b2    = (const float*)d_in[28];

    float* SNb = fsym(g_SN);
    float* SEb = fsym(g_SE);
    float* SCb = fsym(g_SC);
    float* BDCb = fsym(g_BDC);
    float* VCbb = fsym(g_VCb);
    float* SN[2]  = { SNb, SNb + (size_t)NN * HD };
    float* SE[2]  = { SEb, SEb + (size_t)NE * HD };
    float* SC[2]  = { SCb, SCb + (size_t)NC * HD };
    float* BDC[2] = { BDCb, BDCb + (size_t)NC * HD };
    float* VCB[2] = { VCbb, VCbb + (size_t)NC * HD };
    float* UN   = fsym(g_UN);
    float* VN   = fsym(g_VN);
    float* UE   = fsym(g_UE);
    float* BDNE = fsym(g_BDNE);
    float* BDFC = fsym(g_BDFC);
    float* GPN  = fsym(g_GPN);
    float* GPE  = fsym(g_GPE);
    float* GPC  = fsym(g_GPC);
    unsigned* maske = (unsigned*)vsym(g_maske);
    unsigned* maskc = (unsigned*)vsym(g_maskc);
    unsigned char* flage = (unsigned char*)vsym(g_flage);
    unsigned char* flagc = (unsigned char*)vsym(g_flagc);
    float* pooled = fsym(g_pooled);
    float* hs     = fsym(g_hs);
    __half* WTH   = (__half*)vsym(g_WTH);

    __half* wtSelf = WTH;
    __half* wtUpx  = WTH + (size_t)12 * 65536;
    __half* wtUpa  = WTH + (size_t)20 * 65536;
    __half* wtB    = WTH + (size_t)28 * 65536;
    __half* wtP    = WTH + (size_t)36 * 65536;
    __half* wtPr   = WTH + (size_t)37 * 65536;
    __half* wtW1   = WTH + (size_t)38 * 65536;

    JobPack P;
    int jn = 0, jtot = 0;
    auto jreset = [&]() { jn = 0; jtot = 0; };
    auto jadd = [&](const float* A, const float* A2, const __half* B, float* C,
                    const float* bias, int mb, int fl) {
        P.A[jn] = A; P.A2[jn] = A2; P.B[jn] = B; P.C[jn] = C;
        P.bias[jn] = bias; P.flags[jn] = fl; P.cum[jn] = jtot;
        jtot += mb; jn++;
    };
    auto jlaunch = [&](cudaStream_t st) {
        for (int i = jn; i <= MAXJ; i++) P.cum[i] = 0x7fffffff;
        mma_jobs<<<jtot, 256, MMAG_SMEM, st>>>(P);
    };

    // side chain l: bd_scatter(SE[l-1]) -> BDC[l&1] -> memset BDFC (if more layers)
    auto side_chain = [&](const float* AeIn, int reluX, int l) {
        bd_scatter_kernel<<<QC / 8, 256, 0, s2>>>(AeIn, BDFC, flagc,
                                                  cb_b, cb_i, cb_j,
                                                  QC, MAXC, MAXE, reluX);
        jreset();
        jadd(BDFC, 0, wtB + (size_t)(l * 2 + 1) * 65536, BDC[l & 1], 0, NC / 128, 0);
        jlaunch(s2);
        if (l < NLAY - 1)
            cudaMemsetAsync(BDFC, 0, (size_t)NC * HD * sizeof(float), s2);
    };
    // VC/SC jobs for layer l (l >= 1), on s2
    auto vcsc = [&](int l) {
        const float* Ac  = SC[(l - 1) & 1];
        const float* Ac2 = BDC[(l - 1) & 1];
        jreset();
        jadd(Ac, Ac2, wtUpa + (size_t)(l * 2 + 1) * 65536, VCB[l & 1], 0, NC / 128, 1);
        jadd(Ac, Ac2, wtSelf + (size_t)(l * 3 + 2) * 65536, SC[l & 1],
             bself + (size_t)(l * 3 + 2) * HD, NC / 128, 1);
        jlaunch(s2);
        cudaEventRecord(evC[l], s2);
    };

    // ---- setup (main stream) ----
    cudaMemsetAsync(maske, 0, ((size_t)BSZ * MAXE * MAXN / 32) * sizeof(unsigned));
    cudaMemsetAsync(maskc, 0, ((size_t)BSZ * MAXC * MAXE / 32) * sizeof(unsigned));
    cudaMemsetAsync(BDFC, 0, (size_t)NC * HD * sizeof(float));
    dedup2_kernel<<<(QE + QC) / 256, 256>>>(eb_b, eb_i, eb_j, cb_b, cb_i, cb_j,
                                            maske, maskc, flage, flagc);
    transpose_all<<<dim3(16, 8, 41), dim3(32, 8)>>>(Wself, Wupx, Wupa, Wb, Wp, Wp_r, W1, WTH);
    cudaEventRecord(evS, 0);

    // s2: side chain 0 (concurrent with mega(0))
    cudaStreamWaitEvent(s2, evS, 0);
    side_chain(x_e, 0, 0);

    const float* An = x_n;
    const float* Ae = x_e;

    for (int l = 0; l < NLAY; l++) {
        int q = l & 1;
        __half* wUpxN = wtUpx + (size_t)(l * 2 + 0) * 65536;
        __half* wUpxE = wtUpx + (size_t)(l * 2 + 1) * 65536;
        __half* wUpaN = wtUpa + (size_t)(l * 2 + 0) * 65536;
        __half* wBe   = wtB   + (size_t)(l * 2 + 0) * 65536;
        __half* wSn   = wtSelf + (size_t)(l * 3 + 0) * 65536;
        __half* wSe   = wtSelf + (size_t)(l * 3 + 1) * 65536;
        const float* bn = bself + (size_t)(l * 3 + 0) * HD;
        const float* be = bself + (size_t)(l * 3 + 1) * HD;
        int rA = (l > 0) ? 1 : 0;

        jreset();
        jadd(An, 0, wUpxN, UN,    0,  NN / 128, rA);
        jadd(An, 0, wBe,   BDNE,  0,  NN / 128, rA);
        jadd(An, 0, wSn,   SN[q], bn, NN / 128, rA);
        jadd(Ae, 0, wUpaN, VN,    0,  NE / 128, rA);
        jadd(Ae, 0, wUpxE, UE,    0,  NE / 128, rA);
        jadd(Ae, 0, wSe,   SE[q], be, NE / 128, rA);
        if (l == 0) {
            // layer-0 cell jobs stay on main (inputs are raw x_c)
            jadd(x_c, 0, wtUpa + (size_t)1 * 65536, VCB[0], 0, NC / 128, 0);
            jadd(x_c, 0, wtSelf + (size_t)2 * 65536, SC[0],
                 bself + (size_t)2 * HD, NC / 128, 0);
            jadd(x_n, 0, wtPr, GPN, 0, NN / 128, 0);
            jadd(x_e, 0, wtPr, GPE, 0, NE / 128, 0);
            jadd(x_c, 0, wtPr, GPC, 0, NC / 128, 0);
        }
        jlaunch(0);

        if (l == 0) {
            cudaEventRecord(evM0, 0);
            cudaStreamWaitEvent(s2, evM0, 0);   // VCSC(1) needs SC[0]
            vcsc(1);
        }
        if (l >= 1) cudaStreamWaitEvent(0, evC[l], 0);   // fused_scatter needs VCB[l&1]

        fused_scatter<<<FS_GRID, 256>>>(
            UN, VN, SN[q], UE, VCB[q], SE[q], BDNE, flage,
            n_up_b, n_up_i, n_up_j, n_up_e,
            e_up_b, e_up_i, e_up_j, e_up_c,
            eb_b, eb_i, eb_j);

        if (l < NLAY - 1) {
            cudaEventRecord(evFS[l], 0);
            cudaStreamWaitEvent(s2, evFS[l], 0);
            side_chain(SE[q], 1, l + 1);        // reads finalized SE[l]
            if (l + 1 < NLAY - 0 && l + 2 <= 3) {
                vcsc(l + 2);                    // VCSC(l+2): all deps on s2
            } else {
                // after side_chain(3): gate GEMM for cell dim on s2
                jreset();
                jadd(SC[1], BDC[1], wtP, VCB[0], 0, NC / 128, 1);
                jlaunch(s2);
                cudaEventRecord(evC[4], s2);
            }
        }

        An = SN[q]; Ae = SE[q];
    }

    // ---- final gate GEMMs for node/edge dims (main) ----
    jreset();
    jadd(An, 0, wtP, UN, 0, NN / 128, 1);
    jadd(Ae, 0, wtP, VN, 0, NE / 128, 1);
    jlaunch(0);

    // pool needs cell gate + BDC[1] from s2
    cudaStreamWaitEvent(0, evC[4], 0);
    pool3_kernel<<<3 * BSZ, HD>>>(An, Ae, SC[1], BDC[1], UN, VN, VCB[0],
                                  GPN, GPE, GPC, bp, pooled);

    jreset();
    for (int i = 0; i < 3; i++) {
        __half* w1 = wtW1 + (size_t)i * 512 * 256;
        jadd(pooled + (size_t)i * BSZ * HD, 0, w1,
             hs + (size_t)(i * 2 + 0) * BSZ * 256, b1 + i * 512,       BSZ / 128, 2);
        jadd(pooled + (size_t)i * BSZ * HD, 0, w1 + (size_t)256 * 256,
             hs + (size_t)(i * 2 + 1) * BSZ * 256, b1 + i * 512 + 256, BSZ / 128, 2);
    }
    jlaunch(0);

    final_out_kernel<<<BSZ, 32>>>(hs, W2, b2, (float*)d_out);
}

// round 16
// speedup vs baseline: 1.0129x; 1.0129x over previous
#include <cuda_runtime.h>
#include <cuda_fp16.h>
#include <cstdint>

// ---------------- problem constants ----------------
#define HD    256
#define BSZ   256
#define MAXN  128
#define MAXE  256
#define MAXC  64
#define NLAY  4
#define OUTD  10
#define PN    131072
#define PE    98304
#define QE    131072
#define QC    65536

#define NN (BSZ*MAXN)
#define NE (BSZ*MAXE)
#define NC (BSZ*MAXC)

#define WTF ((size_t)38*65536 + (size_t)3*512*256)

// ---------------- device scratch ----------------
__device__ float g_SN[2][(size_t)NN*HD];
__device__ float g_SE[2][(size_t)NE*HD];
__device__ float g_SC[2][(size_t)NC*HD];
__device__ float g_BDC[2][(size_t)NC*HD];
__device__ float g_UN[(size_t)NN*HD];
__device__ float g_VN[(size_t)NE*HD];
__device__ float g_UE[(size_t)NE*HD];
__device__ float g_VC[(size_t)NC*HD];
__device__ float g_BDNE[(size_t)NN*HD];
__device__ float g_BDFC[(size_t)NC*HD];
__device__ float g_GPN[(size_t)NN*HD];
__device__ float g_GPE[(size_t)NE*HD];
__device__ float g_GPC[(size_t)NC*HD];
__device__ unsigned g_maske[(size_t)BSZ*MAXE*MAXN/32];
__device__ unsigned g_maskc[(size_t)BSZ*MAXC*MAXE/32];
__device__ unsigned char g_flage[QE];
__device__ unsigned char g_flagc[QC];
__device__ float g_pooled[3][(size_t)BSZ*HD];
__device__ float g_hs[6][(size_t)BSZ*256];
__device__ __align__(16) __half g_WTH[2*WTF];

// ---------------- PTX helpers (base ISA only) ----------------
__device__ __forceinline__ uint32_t s2u(const void* p) {
    uint32_t a;
    asm("{ .reg .u64 t; cvta.to.shared.u64 t, %1; cvt.u32.u64 %0, t; }"
        : "=r"(a) : "l"(p));
    return a;
}

__device__ __forceinline__ void cp16(uint32_t sa, const void* g) {
    asm volatile("cp.async.cg.shared.global [%0], [%1], 16;" :: "r"(sa), "l"(g));
}
#define CP_COMMIT() asm volatile("cp.async.commit_group;" ::: "memory")
#define CP_WAIT(n)  asm volatile("cp.async.wait_group %0;" :: "n"(n) : "memory")

__device__ __forceinline__ void mma16(float* d, const uint32_t* a, const uint32_t* b) {
    asm volatile(
        "mma.sync.aligned.m16n8k16.row.col.f32.f16.f16.f32 "
        "{%0,%1,%2,%3}, {%4,%5,%6,%7}, {%8,%9}, {%0,%1,%2,%3};"
        : "+f"(d[0]), "+f"(d[1]), "+f"(d[2]), "+f"(d[3])
        : "r"(a[0]), "r"(a[1]), "r"(a[2]), "r"(a[3]), "r"(b[0]), "r"(b[1]));
}

__device__ __forceinline__ void ldm_x4(uint32_t* r, uint32_t sa) {
    asm volatile("ldmatrix.sync.aligned.m8n8.x4.shared.b16 {%0,%1,%2,%3}, [%4];"
                 : "=r"(r[0]), "=r"(r[1]), "=r"(r[2]), "=r"(r[3]) : "r"(sa));
}

__device__ __forceinline__ void red4(float* p, float4 v) {
    asm volatile("red.global.add.v4.f32 [%0], {%1, %2, %3, %4};"
                 :: "l"(p), "f"(v.x), "f"(v.y), "f"(v.z), "f"(v.w) : "memory");
}

__device__ __forceinline__ uint32_t h2u(__half2 h) {
    return *reinterpret_cast<uint32_t*>(&h);
}

// ---------------- job table ----------------
#define MAXJ 12
struct JobPack {
    const float*  A[MAXJ];
    const float*  A2[MAXJ];
    const __half* B[MAXJ];
    float*        C[MAXJ];
    const float*  bias[MAXJ];
    int cum[MAXJ + 1];
    int flags[MAXJ];            // 1 reluA, 2 reluE, 4 accC
};

// ---------------- fp16x3 job-table tensor-core GEMM ----------------
#define PITCH 112
#define A_PLANE (128*PITCH)
#define B_PLANE (256*PITCH)
#define STAGE_B (2*A_PLANE + 2*B_PLANE)
#define MMAG_SMEM (2*STAGE_B)

__global__ __launch_bounds__(256, 1) void mma_jobs(JobPack P)
{
    extern __shared__ __align__(16) char smem[];
    const int tid = threadIdx.x;
    const int wid = tid >> 5, lane = tid & 31;
    const int wm = wid & 1;
    const int wn = wid >> 1;
    const int g = lane >> 2, t = lane & 3;
    const uint32_t sb = s2u(smem);

    int ji = 0;
    #pragma unroll
    for (int i = 1; i < MAXJ; i++)
        if ((int)blockIdx.x >= P.cum[i]) ji++;
    const int m0 = (blockIdx.x - P.cum[ji]) * 128;

    const float*  A    = P.A[ji];
    const float*  A2   = P.A2[ji];
    const __half* B0   = P.B[ji];
    const __half* B1   = B0 + WTF;
    float*        C    = P.C[ji];
    const float*  bias = P.bias[ji];
    const int     fl   = P.flags[ji];
    const int reluA = fl & 1, reluE = fl & 2, accC = fl & 4;

    const float* Ag  = A + (size_t)m0 * 256;
    const float* A2g = A2 ? A2 + (size_t)m0 * 256 : nullptr;

    float acc4[4][8][4];
    #pragma unroll
    for (int i = 0; i < 4; i++)
        #pragma unroll
        for (int j = 0; j < 8; j++)
            #pragma unroll
            for (int k = 0; k < 4; k++) acc4[i][j][k] = 0.f;

    float4 ra[4];

    auto ldgA = [&](int c) {
        #pragma unroll
        for (int i = 0; i < 4; i++) {
            int idx = i * 256 + tid;
            int row = idx >> 3, q = idx & 7;
            ra[i] = *reinterpret_cast<const float4*>(
                Ag + (size_t)row * 256 + c * 32 + q * 4);
        }
        if (A2g) {
            #pragma unroll
            for (int i = 0; i < 4; i++) {
                int idx = i * 256 + tid;
                int row = idx >> 3, q = idx & 7;
                float4 u = *reinterpret_cast<const float4*>(
                    A2g + (size_t)row * 256 + c * 32 + q * 4);
                ra[i].x += u.x; ra[i].y += u.y; ra[i].z += u.z; ra[i].w += u.w;
            }
        }
    };
    auto cvtstsA = [&](int stage) {
        #pragma unroll
        for (int i = 0; i < 4; i++) {
            int idx = i * 256 + tid;
            int row = idx >> 3, q = idx & 7;
            float4 x = ra[i];
            if (reluA) {
                x.x = fmaxf(x.x, 0.f); x.y = fmaxf(x.y, 0.f);
                x.z = fmaxf(x.z, 0.f); x.w = fmaxf(x.w, 0.f);
            }
            __half2 h0a = __floats2half2_rn(x.x, x.y);
            __half2 h0b = __floats2half2_rn(x.z, x.w);
            float2 f0a = __half22float2(h0a);
            float2 f0b = __half22float2(h0b);
            __half2 h1a = __floats2half2_rn(x.x - f0a.x, x.y - f0a.y);
            __half2 h1b = __floats2half2_rn(x.z - f0b.x, x.w - f0b.y);
            uint32_t off = (uint32_t)(row * PITCH + q * 8);
            *reinterpret_cast<uint2*>(smem + stage * STAGE_B + off) =
                make_uint2(h2u(h0a), h2u(h0b));
            *reinterpret_cast<uint2*>(smem + stage * STAGE_B + A_PLANE + off) =
                make_uint2(h2u(h1a), h2u(h1b));
        }
    };
    auto cpB = [&](int c, int stage) {
        uint32_t b0 = sb + (uint32_t)(stage * STAGE_B + 2 * A_PLANE);
        uint32_t b1 = b0 + B_PLANE;
        #pragma unroll
        for (int i = 0; i < 8; i++) {
            int idx = i * 256 + tid;
            int row = idx >> 3;
            int s = idx & 7;
            int plane = s >> 2, seg = s & 3;
            uint32_t dst = (plane ? b1 : b0) + (uint32_t)(row * PITCH + seg * 16);
            const __half* src = (plane ? B1 : B0) + (size_t)row * 256 + c * 32 + seg * 8;
            cp16(dst, src);
        }
        CP_COMMIT();
    };

    const int ar0 = wm * 64;
    const int bc0 = wn * 64;
    const uint32_t aoff = (uint32_t)((ar0 + (lane & 15)) * PITCH + (lane >> 4) * 16);
    const int grp = lane >> 3;
    const uint32_t boff = (uint32_t)((bc0 + ((grp >> 1) << 3) + (lane & 7)) * PITCH
                                     + (grp & 1) * 16);

    ldgA(0); cvtstsA(0); cpB(0, 0);
    ldgA(1);

    #pragma unroll
    for (int c = 0; c < 8; c++) {
        CP_WAIT(0);
        __syncthreads();
        if (c < 7) cpB(c + 1, (c + 1) & 1);

        const uint32_t st = sb + (uint32_t)(c & 1) * STAGE_B;

        #pragma unroll
        for (int ks = 0; ks < 2; ks++) {
            const uint32_t ko = ks * 32;
            uint32_t a0[4][4], a1[4][4];
            #pragma unroll
            for (int mt = 0; mt < 4; mt++) {
                uint32_t ad = st + aoff + (uint32_t)(mt * 16 * PITCH) + ko;
                ldm_x4(a0[mt], ad);
                ldm_x4(a1[mt], ad + A_PLANE);
            }
            uint32_t b0r[8][2], b1r[8][2];
            #pragma unroll
            for (int q = 0; q < 4; q++) {
                uint32_t bd = st + 2 * A_PLANE + boff + (uint32_t)(q * 16 * PITCH) + ko;
                uint32_t r[4];
                ldm_x4(r, bd);
                b0r[2*q][0] = r[0]; b0r[2*q][1] = r[1];
                b0r[2*q+1][0] = r[2]; b0r[2*q+1][1] = r[3];
                ldm_x4(r, bd + B_PLANE);
                b1r[2*q][0] = r[0]; b1r[2*q][1] = r[1];
                b1r[2*q+1][0] = r[2]; b1r[2*q+1][1] = r[3];
            }
            #pragma unroll
            for (int mt = 0; mt < 4; mt++)
                #pragma unroll
                for (int nt = 0; nt < 8; nt++)
                    mma16(acc4[mt][nt], a0[mt], b0r[nt]);
            #pragma unroll
            for (int mt = 0; mt < 4; mt++)
                #pragma unroll
                for (int nt = 0; nt < 8; nt++)
                    mma16(acc4[mt][nt], a0[mt], b1r[nt]);
            #pragma unroll
            for (int mt = 0; mt < 4; mt++)
                #pragma unroll
                for (int nt = 0; nt < 8; nt++)
                    mma16(acc4[mt][nt], a1[mt], b0r[nt]);
        }

        if (c < 7) cvtstsA((c + 1) & 1);
        if (c < 6) ldgA(c + 2);
    }

    #pragma unroll
    for (int mt = 0; mt < 4; mt++) {
        #pragma unroll
        for (int nt = 0; nt < 8; nt++) {
            const int col = wn * 64 + nt * 8 + 2 * t;
            #pragma unroll
            for (int h = 0; h < 2; h++) {
                const int row = m0 + wm * 64 + mt * 16 + g + h * 8;
                const size_t off = (size_t)row * 256 + col;
                float v0 = acc4[mt][nt][2 * h];
                float v1 = acc4[mt][nt][2 * h + 1];
                if (bias)  { v0 += bias[col]; v1 += bias[col + 1]; }
                if (reluE) { v0 = fmaxf(v0, 0.f); v1 = fmaxf(v1, 0.f); }
                if (accC)  { float2 a = *reinterpret_cast<const float2*>(C + off);
                             v0 += a.x; v1 += a.y; }
                *reinterpret_cast<float2*>(C + off) = make_float2(v0, v1);
            }
        }
    }
}

// ---------------- weight transpose + fp16 h0/h1 split ----------------
__global__ void transpose_all(
    const float* __restrict__ Wself, const float* __restrict__ Wupx,
    const float* __restrict__ Wupa,  const float* __restrict__ Wb,
    const float* __restrict__ Wp,    const float* __restrict__ Wp_r,
    const float* __restrict__ W1,    __half* __restrict__ out)
{
    int z = blockIdx.z;
    const float* I;
    __half* O;
    int N;
    if (z < 12)      { I = Wself + (size_t)z * 65536;        O = out + (size_t)z * 65536;  N = 256; }
    else if (z < 20) { I = Wupx + (size_t)(z - 12) * 65536;  O = out + (size_t)z * 65536;  N = 256; }
    else if (z < 28) { I = Wupa + (size_t)(z - 20) * 65536;  O = out + (size_t)z * 65536;  N = 256; }
    else if (z < 36) { I = Wb + (size_t)(z - 28) * 65536;    O = out + (size_t)z * 65536;  N = 256; }
    else if (z == 36){ I = Wp;                               O = out + (size_t)36 * 65536; N = 256; }
    else if (z == 37){ I = Wp_r;                             O = out + (size_t)37 * 65536; N = 256; }
    else             { I = W1 + (size_t)(z - 38) * 512 * 256;
                       O = out + (size_t)38 * 65536 + (size_t)(z - 38) * 512 * 256; N = 512; }
    const int K = 256;
    int n0 = blockIdx.x * 32, k0 = blockIdx.y * 32;
    if (n0 >= N) return;
    __shared__ float tbuf[32][33];
    int x = threadIdx.x, y = threadIdx.y;
    #pragma unroll
    for (int dy = 0; dy < 32; dy += 8)
        tbuf[y + dy][x] = I[(size_t)(k0 + y + dy) * N + n0 + x];
    __syncthreads();
    #pragma unroll
    for (int dy = 0; dy < 32; dy += 8) {
        float w = tbuf[x][y + dy];
        __half h0 = __float2half_rn(w);
        __half h1 = __float2half_rn(w - __half2float(h0));
        size_t o = (size_t)(n0 + y + dy) * K + k0 + x;
        O[o] = h0;
        O[o + WTF] = h1;
    }
}

// ---------------- merged dedup ----------------
__global__ void dedup2_kernel(
    const int* __restrict__ eb_b, const int* __restrict__ eb_i,
    const int* __restrict__ eb_j,
    const int* __restrict__ cb_b, const int* __restrict__ cb_i,
    const int* __restrict__ cb_j,
    unsigned* __restrict__ maske, unsigned* __restrict__ maskc,
    unsigned char* __restrict__ flage, unsigned char* __restrict__ flagc)
{
    int q = blockIdx.x * blockDim.x + threadIdx.x;
    if (q < QE) {
        unsigned flat = ((unsigned)eb_b[q] * MAXE + eb_i[q]) * MAXN + eb_j[q];
        unsigned bit = 1u << (flat & 31u);
        unsigned old = atomicOr(&maske[flat >> 5], bit);
        flage[q] = (old & bit) ? 0 : 1;
    } else {
        int r = q - QE;
        if (r < QC) {
            unsigned flat = ((unsigned)cb_b[r] * MAXC + cb_i[r]) * MAXE + cb_j[r];
            unsigned bit = 1u << (flat & 31u);
            unsigned old = atomicOr(&maskc[flat >> 5], bit);
            flagc[r] = (old & bit) ? 0 : 1;
        }
    }
}

// ---------------- cell-boundary scatter ----------------
__global__ void bd_scatter_kernel(
    const float* __restrict__ X, float* __restrict__ out,
    const unsigned char* __restrict__ flag,
    const int* __restrict__ qb, const int* __restrict__ qi, const int* __restrict__ qj,
    int Q, int mult_i, int mult_j, int reluX)
{
    int w = (blockIdx.x * blockDim.x + threadIdx.x) >> 5;
    int lane = threadIdx.x & 31;
    if (w >= Q) return;
    if (!flag[w]) return;
    int b = qb[w];
    size_t dst = ((size_t)b * mult_i + qi[w]) * HD;
    size_t src = ((size_t)b * mult_j + qj[w]) * HD;
    #pragma unroll
    for (int t = 0; t < 2; t++) {
        int c = (lane << 2) + (t << 7);
        float4 v = *reinterpret_cast<const float4*>(X + src + c);
        if (reluX) {
            v.x = fmaxf(v.x, 0.f); v.y = fmaxf(v.y, 0.f);
            v.z = fmaxf(v.z, 0.f); v.w = fmaxf(v.w, 0.f);
        }
        red4(out + dst + c, v);
    }
}

// ---------------- fused per-layer scatter: 3 segments ----------------
#define FS_SEG0 (PN/8)
#define FS_SEG1 (FS_SEG0 + PE/8)
#define FS_GRID (FS_SEG1 + QE/8)

__global__ void fused_scatter(
    const float* __restrict__ UN, const float* __restrict__ VN,
    float* __restrict__ SN_,
    const float* __restrict__ UE, const float* __restrict__ VC,
    float* __restrict__ SE_,
    const float* __restrict__ BDNE, const unsigned char* __restrict__ flage,
    const int* __restrict__ nb, const int* __restrict__ ni,
    const int* __restrict__ nj, const int* __restrict__ na,
    const int* __restrict__ pb, const int* __restrict__ pi,
    const int* __restrict__ pj, const int* __restrict__ pa,
    const int* __restrict__ qb, const int* __restrict__ qi,
    const int* __restrict__ qj)
{
    const int blk = blockIdx.x;
    const int lane = threadIdx.x & 31;

    if (blk < FS_SEG0) {
        int w = blk * 8 + (threadIdx.x >> 5);
        int b = nb[w];
        size_t dst = ((size_t)b * MAXN + ni[w]) * HD;
        size_t src = ((size_t)b * MAXN + nj[w]) * HD;
        size_t att = ((size_t)b * MAXE + na[w]) * HD;
        #pragma unroll
        for (int t = 0; t < 2; t++) {
            int c = (lane << 2) + (t << 7);
            float4 u = *reinterpret_cast<const float4*>(UN + src + c);
            float4 v = *reinterpret_cast<const float4*>(VN + att + c);
            float4 r;
            r.x = fmaxf(u.x + v.x, 0.f);
            r.y = fmaxf(u.y + v.y, 0.f);
            r.z = fmaxf(u.z + v.z, 0.f);
            r.w = fmaxf(u.w + v.w, 0.f);
            red4(SN_ + dst + c, r);
        }
    } else if (blk < FS_SEG1) {
        int w = (blk - FS_SEG0) * 8 + (threadIdx.x >> 5);
        int b = pb[w];
        size_t dst = ((size_t)b * MAXE + pi[w]) * HD;
        size_t src = ((size_t)b * MAXE + pj[w]) * HD;
        size_t att = ((size_t)b * MAXC + pa[w]) * HD;
        #pragma unroll
        for (int t = 0; t < 2; t++) {
            int c = (lane << 2) + (t << 7);
            float4 u = *reinterpret_cast<const float4*>(UE + src + c);
            float4 v = *reinterpret_cast<const float4*>(VC + att + c);
            float4 r;
            r.x = fmaxf(u.x + v.x, 0.f);
            r.y = fmaxf(u.y + v.y, 0.f);
            r.z = fmaxf(u.z + v.z, 0.f);
            r.w = fmaxf(u.w + v.w, 0.f);
            red4(SE_ + dst + c, r);
        }
    } else {
        int w = (blk - FS_SEG1) * 8 + (threadIdx.x >> 5);
        if (!flage[w]) return;
        int b = qb[w];
        size_t dst = ((size_t)b * MAXE + qi[w]) * HD;
        size_t src = ((size_t)b * MAXN + qj[w]) * HD;
        #pragma unroll
        for (int t = 0; t < 2; t++) {
            int c = (lane << 2) + (t << 7);
            float4 v = *reinterpret_cast<const float4*>(BDNE + src + c);
            red4(SE_ + dst + c, v);
        }
    }
}

// ---------------- merged gated pooling ----------------
__global__ void pool3_kernel(
    const float* __restrict__ Xn, const float* __restrict__ Xe,
    const float* __restrict__ Xc, const float* __restrict__ Xc2,
    const float* __restrict__ Gn1, const float* __restrict__ Ge1,
    const float* __restrict__ Gc1,
    const float* __restrict__ Gn2, const float* __restrict__ Ge2,
    const float* __restrict__ Gc2,
    const float* __restrict__ bp, float* __restrict__ out)
{
    const int seg = blockIdx.x >> 8;
    const int b = blockIdx.x & 255;
    const int h = threadIdx.x;
    const float* X  = (seg == 0) ? Xn  : ((seg == 1) ? Xe  : Xc);
    const float* X2 = (seg == 2) ? Xc2 : nullptr;
    const float* G1 = (seg == 0) ? Gn1 : ((seg == 1) ? Ge1 : Gc1);
    const float* G2 = (seg == 0) ? Gn2 : ((seg == 1) ? Ge2 : Gc2);
    const int per = (seg == 0) ? MAXN : ((seg == 1) ? MAXE : MAXC);
    float bias = bp[h];
    float acc = 0.f;
    size_t base = (size_t)b * per * HD + h;
    for (int n = 0; n < per; n++) {
        size_t idx = base + (size_t)n * HD;
        float gg = G1[idx] + G2[idx] + bias;
        float w = 1.f / (1.f + expf(-gg));
        float x = X[idx];
        if (X2) x += X2[idx];
        x = fmaxf(x, 0.f);
        acc = fmaf(w, x, acc);
    }
    out[(size_t)seg * BSZ * HD + (size_t)b * HD + h] = acc;
}

// ---------------- final projection ----------------
__global__ void final_out_kernel(
    const float* __restrict__ hs, const float* __restrict__ W2,
    const float* __restrict__ b2, float* __restrict__ out)
{
    int b = blockIdx.x;
    int o = threadIdx.x;
    if (o >= OUTD) return;
    const size_t S = (size_t)BSZ * 256;
    float acc = b2[o];
    for (int k = 0; k < 256; k++) {
        size_t bk = (size_t)b * 256 + k;
        float a = hs[0 * S + bk] + hs[2 * S + bk] + hs[4 * S + bk];
        float c = hs[1 * S + bk] + hs[3 * S + bk] + hs[5 * S + bk];
        acc = fmaf(a, W2[k * OUTD + o], acc);
        acc = fmaf(c, W2[(256 + k) * OUTD + o], acc);
    }
    out[b * OUTD + o] = acc;
}

// ---------------- host side ----------------
static void* vsym(const void* symbol) {
    void* p = nullptr;
    cudaGetSymbolAddress(&p, symbol);
    return p;
}
static float* fsym(const void* s) { return (float*)vsym(s); }

extern "C" void kernel_launch(void* const* d_in, const int* in_sizes, int n_in,
                              void* d_out, int out_size)
{
    (void)in_sizes; (void)n_in; (void)out_size;

    static cudaStream_t s2 = nullptr;
    static cudaEvent_t evA = nullptr, evB0 = nullptr, evB1 = nullptr, evGP = nullptr;
    if (!s2) {
        cudaStreamCreateWithFlags(&s2, cudaStreamNonBlocking);
        cudaEventCreateWithFlags(&evA,  cudaEventDisableTiming);
        cudaEventCreateWithFlags(&evB0, cudaEventDisableTiming);
        cudaEventCreateWithFlags(&evB1, cudaEventDisableTiming);
        cudaEventCreateWithFlags(&evGP, cudaEventDisableTiming);
    }
    cudaEvent_t evB[2] = { evB0, evB1 };

    cudaFuncSetAttribute(mma_jobs, cudaFuncAttributeMaxDynamicSharedMemorySize, MMAG_SMEM);

    const float* x_n   = (const float*)d_in[0];
    const float* x_e   = (const float*)d_in[1];
    const float* x_c   = (const float*)d_in[2];
    const int* n_up_b  = (const int*)d_in[3];
    const int* n_up_i  = (const int*)d_in[4];
    const int* n_up_j  = (const int*)d_in[5];
    const int* n_up_e  = (const int*)d_in[6];
    const int* e_up_b  = (const int*)d_in[7];
    const int* e_up_i  = (const int*)d_in[8];
    const int* e_up_j  = (const int*)d_in[9];
    const int* e_up_c  = (const int*)d_in[10];
    const int* eb_b    = (const int*)d_in[11];
    const int* eb_i    = (const int*)d_in[12];
    const int* eb_j    = (const int*)d_in[13];
    const int* cb_b    = (const int*)d_in[14];
    const int* cb_i    = (const int*)d_in[15];
    const int* cb_j    = (const int*)d_in[16];
    const float* Wself = (const float*)d_in[17];
    const float* bself = (const float*)d_in[18];
    const float* Wupx  = (const float*)d_in[19];
    const float* Wupa  = (const float*)d_in[20];
    const float* Wb    = (const float*)d_in[21];
    const float* Wp    = (const float*)d_in[22];
    const float* Wp_r  = (const float*)d_in[23];
    const float* bp    = (const float*)d_in[24];
    const float* W1    = (const float*)d_in[25];
    const float* b1    = (const float*)d_in[26];
    const float* W2    = (const float*)d_in[27];
    const float* b2    = (const float*)d_in[28];

    float* SNb = fsym(g_SN);
    float* SEb = fsym(g_SE);
    float* SCb = fsym(g_SC);
    float* BDCb = fsym(g_BDC);
    float* SN[2]  = { SNb, SNb + (size_t)NN * HD };
    float* SE[2]  = { SEb, SEb + (size_t)NE * HD };
    float* SC[2]  = { SCb, SCb + (size_t)NC * HD };
    float* BDC[2] = { BDCb, BDCb + (size_t)NC * HD };
    float* UN   = fsym(g_UN);
    float* VN   = fsym(g_VN);
    float* UE   = fsym(g_UE);
    float* VC   = fsym(g_VC);
    float* BDNE = fsym(g_BDNE);
    float* BDFC = fsym(g_BDFC);
    float* GPN  = fsym(g_GPN);
    float* GPE  = fsym(g_GPE);
    float* GPC  = fsym(g_GPC);
    unsigned* maske = (unsigned*)vsym(g_maske);
    unsigned* maskc = (unsigned*)vsym(g_maskc);
    unsigned char* flage = (unsigned char*)vsym(g_flage);
    unsigned char* flagc = (unsigned char*)vsym(g_flagc);
    float* pooled = fsym(g_pooled);
    float* hs     = fsym(g_hs);
    __half* WTH   = (__half*)vsym(g_WTH);

    __half* wtSelf = WTH;
    __half* wtUpx  = WTH + (size_t)12 * 65536;
    __half* wtUpa  = WTH + (size_t)20 * 65536;
    __half* wtB    = WTH + (size_t)28 * 65536;
    __half* wtP    = WTH + (size_t)36 * 65536;
    __half* wtPr   = WTH + (size_t)37 * 65536;
    __half* wtW1   = WTH + (size_t)38 * 65536;

    JobPack P;
    int jn = 0, jtot = 0;
    auto jreset = [&]() { jn = 0; jtot = 0; };
    auto jadd = [&](const float* A, const float* A2, const __half* B, float* C,
                    const float* bias, int mb, int fl) {
        P.A[jn] = A; P.A2[jn] = A2; P.B[jn] = B; P.C[jn] = C;
        P.bias[jn] = bias; P.flags[jn] = fl; P.cum[jn] = jtot;
        jtot += mb; jn++;
    };
    auto jlaunch = [&](cudaStream_t st) {
        for (int i = jn; i <= MAXJ; i++) P.cum[i] = 0x7fffffff;
        mma_jobs<<<jtot, 256, MMAG_SMEM, st>>>(P);
    };

    // side-chain l: bd_scatter -> BDC[l&1] -> memset BDFC (for next layer)
    auto side_chain = [&](const float* AeIn, int reluX, int l) {
        bd_scatter_kernel<<<QC / 8, 256, 0, s2>>>(AeIn, BDFC, flagc,
                                                  cb_b, cb_i, cb_j,
                                                  QC, MAXC, MAXE, reluX);
        JobPack Q2;
        Q2.A[0] = BDFC; Q2.A2[0] = 0;
        Q2.B[0] = wtB + (size_t)(l * 2 + 1) * 65536;
        Q2.C[0] = BDC[l & 1]; Q2.bias[0] = 0; Q2.flags[0] = 0; Q2.cum[0] = 0;
        for (int i = 1; i <= MAXJ; i++) Q2.cum[i] = 0x7fffffff;
        mma_jobs<<<NC / 128, 256, MMAG_SMEM, s2>>>(Q2);
        if (l < NLAY - 1)
            cudaMemsetAsync(BDFC, 0, (size_t)NC * HD * sizeof(float), s2);
        cudaEventRecord(evB[l & 1], s2);
    };

    // ---- setup (default stream) ----
    cudaMemsetAsync(maske, 0, ((size_t)BSZ * MAXE * MAXN / 32) * sizeof(unsigned));
    cudaMemsetAsync(maskc, 0, ((size_t)BSZ * MAXC * MAXE / 32) * sizeof(unsigned));
    cudaMemsetAsync(BDFC, 0, (size_t)NC * HD * sizeof(float));
    dedup2_kernel<<<(QE + QC) / 256, 256>>>(eb_b, eb_i, eb_j, cb_b, cb_i, cb_j,
                                            maske, maskc, flage, flagc);
    transpose_all<<<dim3(16, 8, 41), dim3(32, 8)>>>(Wself, Wupx, Wupa, Wb, Wp, Wp_r, W1, WTH);
    cudaEventRecord(evA, 0);

    // side chain for layer 0 (concurrent with mega(0))
    cudaStreamWaitEvent(s2, evA, 0);
    side_chain(x_e, 0, 0);

    const float* An = x_n;
    const float* Ae = x_e;
    const float* Ac = x_c;
    const float* Ac2 = nullptr;
    int rA = 0;

    for (int l = 0; l < NLAY; l++) {
        int q = l & 1;
        __half* wUpxN = wtUpx + (size_t)(l * 2 + 0) * 65536;
        __half* wUpxE = wtUpx + (size_t)(l * 2 + 1) * 65536;
        __half* wUpaN = wtUpa + (size_t)(l * 2 + 0) * 65536;
        __half* wUpaE = wtUpa + (size_t)(l * 2 + 1) * 65536;
        __half* wBe   = wtB   + (size_t)(l * 2 + 0) * 65536;
        __half* wSn   = wtSelf + (size_t)(l * 3 + 0) * 65536;
        __half* wSe   = wtSelf + (size_t)(l * 3 + 1) * 65536;
        __half* wSc   = wtSelf + (size_t)(l * 3 + 2) * 65536;
        const float* bn = bself + (size_t)(l * 3 + 0) * HD;
        const float* be = bself + (size_t)(l * 3 + 1) * HD;
        const float* bc = bself + (size_t)(l * 3 + 2) * HD;

        // mega(l) needs BDC(l-1) from side stream
        if (l > 0) cudaStreamWaitEvent(0, evB[(l - 1) & 1], 0);

        jreset();
        jadd(An, 0,   wUpxN, UN,    0,  NN / 128, rA);
        jadd(An, 0,   wBe,   BDNE,  0,  NN / 128, rA);
        jadd(An, 0,   wSn,   SN[q], bn, NN / 128, rA);
        jadd(Ae, 0,   wUpaN, VN,    0,  NE / 128, rA);
        jadd(Ae, 0,   wUpxE, UE,    0,  NE / 128, rA);
        jadd(Ae, 0,   wSe,   SE[q], be, NE / 128, rA);
        jadd(Ac, Ac2, wUpaE, VC,    0,  NC / 128, rA);
        jadd(Ac, Ac2, wSc,   SC[q], bc, NC / 128, rA);
        jlaunch(0);

        fused_scatter<<<FS_GRID, 256>>>(
            UN, VN, SN[q], UE, VC, SE[q], BDNE, flage,
            n_up_b, n_up_i, n_up_j, n_up_e,
            e_up_b, e_up_i, e_up_j, e_up_c,
            eb_b, eb_i, eb_j);

        if (l < NLAY - 1) {
            cudaEventRecord(evA, 0);
            cudaStreamWaitEvent(s2, evA, 0);
            side_chain(SE[q], 1, l + 1);        // reads finalized SE[l]
            if (l == 0) {
                // pool-ref gate GEMMs ride s2 here: first ~105us overlap
                // main's fused_scatter(0)/memory-bound phases.
                jreset();
                jadd(x_n, 0, wtPr, GPN, 0, NN / 128, 0);
                jadd(x_e, 0, wtPr, GPE, 0, NE / 128, 0);
                jadd(x_c, 0, wtPr, GPC, 0, NC / 128, 0);
                jlaunch(s2);
                cudaEventRecord(evGP, s2);
            }
        }

        An = SN[q]; Ae = SE[q]; Ac = SC[q]; Ac2 = BDC[q];
        rA = 1;
    }

    // final gates need BDC(3) from side stream
    cudaStreamWaitEvent(0, evB[(NLAY - 1) & 1], 0);

    jreset();
    jadd(An, 0,   wtP, UN, 0, NN / 128, 1);
    jadd(Ae, 0,   wtP, VN, 0, NE / 128, 1);
    jadd(Ac, Ac2, wtP, VC, 0, NC / 128, 1);
    jlaunch(0);

    // pooling needs GP gates from s2
    cudaStreamWaitEvent(0, evGP, 0);
    pool3_kernel<<<3 * BSZ, HD>>>(An, Ae, Ac, Ac2, UN, VN, VC, GPN, GPE, GPC,
                                  bp, pooled);

    jreset();
    for (int i = 0; i < 3; i++) {
        __half* w1 = wtW1 + (size_t)i * 512 * 256;
        jadd(pooled + (size_t)i * BSZ * HD, 0, w1,
             hs + (size_t)(i * 2 + 0) * BSZ * 256, b1 + i * 512,       BSZ / 128, 2);
        jadd(pooled + (size_t)i * BSZ * HD, 0, w1 + (size_t)256 * 256,
             hs + (size_t)(i * 2 + 1) * BSZ * 256, b1 + i * 512 + 256, BSZ / 128, 2);
    }
    jlaunch(0);

    final_out_kernel<<<BSZ, 32>>>(hs, W2, b2, (float*)d_out);
}